// round 2
// baseline (speedup 1.0000x reference)
#include <cuda_runtime.h>
#include <cuda_bf16.h>
#include <cstdint>

// LinearUnit (LRU cell single step), pure elementwise:
//   out[b,j] = (in[b,0]+in[b,1]) * bcol[j] + state[b,j] * adiag[j]
//   adiag[j] = j<S ? as_real[j] : as_imag[j-S],  bcol analogous, S = NU/2.
// Reference returns (new_state, new_state); if the harness flattens the tuple,
// out_size == 2*B*NU and we duplicate the tensor.
//
// HBM-bound: ~128 MiB state read + 128/256 MiB write. float4 everywhere.

__global__ __launch_bounds__(256)
void linear_unit_vec4(const float* __restrict__ inputs,   // (B, 2)
                      const float* __restrict__ state,    // (B, NU)
                      const float* __restrict__ as_real,  // (NU,)
                      const float* __restrict__ as_imag,
                      const float* __restrict__ bs_real,
                      const float* __restrict__ bs_imag,
                      float* __restrict__ out,
                      int nu,          // units per row (power-of-two expected)
                      int shalf,       // nu/2
                      long long total4,// B*nu/4
                      long long total, // B*nu
                      int dup)
{
    const long long stride = (long long)gridDim.x * blockDim.x;

    for (long long i4 = (long long)blockIdx.x * blockDim.x + threadIdx.x;
         i4 < total4; i4 += stride) {
        const long long elem = i4 * 4;
        const int row = (int)(elem / nu);
        const int u   = (int)(elem - (long long)row * nu);

        // Broadcast row sum: all threads of a row hit the same 8 bytes (L1/L2).
        const float s = __ldg(&inputs[row * 2]) + __ldg(&inputs[row * 2 + 1]);

        // Param float4: never crosses the real/imag split when shalf % 4 == 0.
        float4 a, b;
        if (u < shalf) {
            a = *reinterpret_cast<const float4*>(as_real + u);
            b = *reinterpret_cast<const float4*>(bs_real + u);
        } else {
            a = *reinterpret_cast<const float4*>(as_imag + (u - shalf));
            b = *reinterpret_cast<const float4*>(bs_imag + (u - shalf));
        }

        const float4 st = *reinterpret_cast<const float4*>(state + elem);

        float4 r;
        r.x = fmaf(st.x, a.x, s * b.x);
        r.y = fmaf(st.y, a.y, s * b.y);
        r.z = fmaf(st.z, a.z, s * b.z);
        r.w = fmaf(st.w, a.w, s * b.w);

        *reinterpret_cast<float4*>(out + elem) = r;
        if (dup) {
            *reinterpret_cast<float4*>(out + total + elem) = r;
        }
    }
}

// Scalar fallback for shapes where NU or S isn't a multiple of 4.
__global__ __launch_bounds__(256)
void linear_unit_scalar(const float* __restrict__ inputs,
                        const float* __restrict__ state,
                        const float* __restrict__ as_real,
                        const float* __restrict__ as_imag,
                        const float* __restrict__ bs_real,
                        const float* __restrict__ bs_imag,
                        float* __restrict__ out,
                        int nu, int shalf,
                        long long total, int dup)
{
    const long long stride = (long long)gridDim.x * blockDim.x;
    for (long long e = (long long)blockIdx.x * blockDim.x + threadIdx.x;
         e < total; e += stride) {
        const int row = (int)(e / nu);
        const int u   = (int)(e - (long long)row * nu);
        const float s = __ldg(&inputs[row * 2]) + __ldg(&inputs[row * 2 + 1]);
        const float a = (u < shalf) ? as_real[u] : as_imag[u - shalf];
        const float b = (u < shalf) ? bs_real[u] : bs_imag[u - shalf];
        const float r = fmaf(state[e], a, s * b);
        out[e] = r;
        if (dup) out[total + e] = r;
    }
}

extern "C" void kernel_launch(void* const* d_in, const int* in_sizes, int n_in,
                              void* d_out, int out_size)
{
    const float* inputs  = (const float*)d_in[0];
    const float* state   = (const float*)d_in[1];
    const float* as_real = (const float*)d_in[2];
    const float* as_imag = (const float*)d_in[3];
    const float* bs_real = (const float*)d_in[4];
    const float* bs_imag = (const float*)d_in[5];
    float* out = (float*)d_out;

    // Derive shapes from the harness (robust to shape variants):
    // inputs is (B,2); as_real is (NU,); state is (B,NU).
    const long long b_sz  = in_sizes[0];        // B*2
    const int       batch = (int)(b_sz / 2);
    const int       nu    = in_sizes[2];        // NU
    const int       shalf = nu / 2;
    const long long total = (long long)batch * nu;
    const int       dup   = ((long long)out_size >= 2 * total) ? 1 : 0;

    const int threads = 256;

    if ((nu % 4 == 0) && (shalf % 4 == 0)) {
        const long long total4 = total / 4;
        long long blocks = (total4 + threads - 1) / threads;
        if (blocks > 1048576) blocks = 1048576;   // grid-stride covers the rest
        linear_unit_vec4<<<(int)blocks, threads>>>(inputs, state, as_real, as_imag,
                                                   bs_real, bs_imag, out,
                                                   nu, shalf, total4, total, dup);
    } else {
        long long blocks = (total + threads - 1) / threads;
        if (blocks > 1048576) blocks = 1048576;
        linear_unit_scalar<<<(int)blocks, threads>>>(inputs, state, as_real, as_imag,
                                                     bs_real, bs_imag, out,
                                                     nu, shalf, total, dup);
    }
}

// round 3
// speedup vs baseline: 1.0549x; 1.0549x over previous
#include <cuda_runtime.h>
#include <cuda_bf16.h>
#include <cstdint>

// LinearUnit (LRU cell single step), pure elementwise:
//   out[b,j] = (in[b,0]+in[b,1]) * bcol[j] + state[b,j] * adiag[j]
//   adiag[j] = j<S ? as_real[j] : as_imag[j-S],  bcol analogous, S = NU/2.
// Output is duplicated (reference returns (new_state, new_state)) when
// out_size == 2*B*NU.
//
// HBM-bound (134 MB read + 268 MB write with dup). Round-3 focus: strip the
// 64-bit division / long-long index math that left ALU at 37.6% and DRAM at
// only 67.7% in Round 2. Power-of-two NU path is pure 32-bit shift/mask,
// one float4 per thread, no loop.

__global__ __launch_bounds__(256)
void linear_unit_pow2(const float2* __restrict__ inputs2,  // (B,2) as float2
                      const float*  __restrict__ state,    // (B, NU)
                      const float*  __restrict__ as_real,  // (NU,)
                      const float*  __restrict__ as_imag,
                      const float*  __restrict__ bs_real,
                      const float*  __restrict__ bs_imag,
                      float* __restrict__ out,
                      int row_shift,    // log2(NU/4): i4 >> row_shift = row
                      int u4_mask,      // (NU/4 - 1)
                      int shalf,        // NU/2
                      unsigned total,   // B*NU  (fits 32-bit: 33.5M)
                      int dup)
{
    const unsigned i4  = blockIdx.x * 256u + threadIdx.x;   // one float4 per thread
    const int row = (int)(i4 >> row_shift);
    const int u   = (int)(i4 & u4_mask) * 4;
    const unsigned elem = ((unsigned)row << (row_shift + 2)) | (unsigned)u;

    // Row broadcast: single 8-byte load, L1-resident across the row's threads.
    const float2 in = __ldg(&inputs2[row]);
    const float  s  = in.x + in.y;

    // Params: float4 never crosses the real/imag split (shalf % 4 == 0 checked host-side).
    float4 a, b;
    if (u < shalf) {
        a = *reinterpret_cast<const float4*>(as_real + u);
        b = *reinterpret_cast<const float4*>(bs_real + u);
    } else {
        a = *reinterpret_cast<const float4*>(as_imag + (u - shalf));
        b = *reinterpret_cast<const float4*>(bs_imag + (u - shalf));
    }

    // Streaming read: state is touched exactly once.
    const float4 st = __ldcs(reinterpret_cast<const float4*>(state + elem));

    float4 r;
    r.x = fmaf(st.x, a.x, s * b.x);
    r.y = fmaf(st.y, a.y, s * b.y);
    r.z = fmaf(st.z, a.z, s * b.z);
    r.w = fmaf(st.w, a.w, s * b.w);

    // Streaming writes: never re-read by this kernel.
    __stcs(reinterpret_cast<float4*>(out + elem), r);
    if (dup) {
        __stcs(reinterpret_cast<float4*>(out + total + elem), r);
    }
}

// Generic fallback (any shape). Grid-stride, 64-bit safe.
__global__ __launch_bounds__(256)
void linear_unit_generic(const float* __restrict__ inputs,
                         const float* __restrict__ state,
                         const float* __restrict__ as_real,
                         const float* __restrict__ as_imag,
                         const float* __restrict__ bs_real,
                         const float* __restrict__ bs_imag,
                         float* __restrict__ out,
                         int nu, int shalf,
                         long long total, int dup)
{
    const long long stride = (long long)gridDim.x * blockDim.x;
    for (long long e = (long long)blockIdx.x * blockDim.x + threadIdx.x;
         e < total; e += stride) {
        const int row = (int)(e / nu);
        const int u   = (int)(e - (long long)row * nu);
        const float s = __ldg(&inputs[row * 2]) + __ldg(&inputs[row * 2 + 1]);
        const float a = (u < shalf) ? as_real[u] : as_imag[u - shalf];
        const float b = (u < shalf) ? bs_real[u] : bs_imag[u - shalf];
        const float r = fmaf(state[e], a, s * b);
        out[e] = r;
        if (dup) out[total + e] = r;
    }
}

static inline int ilog2u(unsigned v) {
    int s = 0;
    while ((1u << s) < v) s++;
    return s;
}

extern "C" void kernel_launch(void* const* d_in, const int* in_sizes, int n_in,
                              void* d_out, int out_size)
{
    const float* inputs  = (const float*)d_in[0];
    const float* state   = (const float*)d_in[1];
    const float* as_real = (const float*)d_in[2];
    const float* as_imag = (const float*)d_in[3];
    const float* bs_real = (const float*)d_in[4];
    const float* bs_imag = (const float*)d_in[5];
    float* out = (float*)d_out;

    // Shapes from harness: inputs (B,2), as_real (NU,), state (B,NU).
    const int       batch = in_sizes[0] / 2;
    const int       nu    = in_sizes[2];
    const int       shalf = nu / 2;
    const long long total = (long long)batch * nu;
    const int       dup   = ((long long)out_size >= 2 * total) ? 1 : 0;

    const bool pow2   = (nu & (nu - 1)) == 0;
    const bool vecok  = (nu % 4 == 0) && (shalf % 4 == 0);
    const long long total4 = total / 4;

    if (pow2 && vecok && total4 % 256 == 0 && total <= 0x7FFFFFFFLL) {
        const int nu4       = nu / 4;
        const int row_shift = ilog2u((unsigned)nu4);
        const int blocks    = (int)(total4 / 256);
        linear_unit_pow2<<<blocks, 256>>>(
            (const float2*)inputs, state, as_real, as_imag, bs_real, bs_imag,
            out, row_shift, nu4 - 1, shalf, (unsigned)total, dup);
    } else {
        long long blocks = (total + 255) / 256;
        if (blocks > 1048576) blocks = 1048576;
        linear_unit_generic<<<(int)blocks, 256>>>(
            inputs, state, as_real, as_imag, bs_real, bs_imag,
            out, nu, shalf, total, dup);
    }
}